// round 3
// baseline (speedup 1.0000x reference)
#include <cuda_runtime.h>
#include <math.h>

// Problem dims
#define BB 256
#define TT 512
#define HH 256
#define G3 768          // 3*H
#define INDIM 75
#define BT (BB*TT)      // 131072

// ---------------- scratch (device globals; no allocations allowed) ---------
__device__ float g_xg[(size_t)BB * TT * G3];     // input-gate preactivations (reused per layer)
__device__ float g_out0[(size_t)BB * TT * HH];   // layer-0 hidden states
__device__ float g_hbuf[2][BB * HH];             // layer-1 h ping-pong
__device__ unsigned g_cnt[TT];                   // per-step arrival counters

// ---------------- tiny kernel: reset barrier counters ----------------------
__global__ void zero_cnt_kernel() {
    int t = threadIdx.x;
    if (t < TT) g_cnt[t] = 0u;
}

__device__ __forceinline__ unsigned f2tf32(float v) {
    unsigned u;
    asm("cvt.rna.tf32.f32 %0, %1;" : "=r"(u) : "f"(v));
    return u;
}

__device__ __forceinline__ void mma_tf32(float c[4], const unsigned a[4], unsigned b0, unsigned b1) {
    asm volatile(
        "mma.sync.aligned.m16n8k8.row.col.f32.tf32.tf32.f32 "
        "{%0,%1,%2,%3}, {%4,%5,%6,%7}, {%8,%9}, {%0,%1,%2,%3};"
        : "+f"(c[0]), "+f"(c[1]), "+f"(c[2]), "+f"(c[3])
        : "r"(a[0]), "r"(a[1]), "r"(a[2]), "r"(a[3]), "r"(b0), "r"(b1));
}

// ---------------- TF32 tensor-core GEMM: C = A[M,K] @ W[N,K]^T + bias ------
#define TBM 128
#define TBN 64
#define TBK 16
#define TPAD 20

__global__ __launch_bounds__(256) void tf32_gemm_bias_kernel(
    const float* __restrict__ A, const float* __restrict__ W,
    const float* __restrict__ bias, float* __restrict__ C,
    int M, int N, int K)
{
    __shared__ unsigned As[TBM * TPAD];
    __shared__ unsigned Bs[TBN * TPAD];

    const int tid = threadIdx.x;
    const int wid = tid >> 5, lane = tid & 31;
    const int g = lane >> 2, t = lane & 3;
    const int wm = wid & 3, wn = wid >> 2;
    const int m0 = blockIdx.y * TBM;
    const int n0 = blockIdx.x * TBN;

    float acc[2][4][4];
#pragma unroll
    for (int mt = 0; mt < 2; mt++)
#pragma unroll
        for (int nt = 0; nt < 4; nt++)
#pragma unroll
            for (int i = 0; i < 4; i++) acc[mt][nt][i] = 0.f;

    const int am = tid >> 4;
    const int ak = tid & 15;
    const int bn = tid >> 2;
    const int bk4 = (tid & 3) * 4;

    float ra[8], rb[4];
    const int nk = (K + TBK - 1) / TBK;

    {
#pragma unroll
        for (int i = 0; i < 8; i++) {
            int m = am + i * 16;
            ra[i] = (ak < K) ? __ldg(&A[(size_t)(m0 + m) * K + ak]) : 0.f;
        }
#pragma unroll
        for (int i = 0; i < 4; i++) {
            int k = bk4 + i;
            rb[i] = (k < K) ? __ldg(&W[(size_t)(n0 + bn) * K + k]) : 0.f;
        }
    }

    for (int kt = 0; kt < nk; kt++) {
#pragma unroll
        for (int i = 0; i < 8; i++) As[(am + i * 16) * TPAD + ak] = f2tf32(ra[i]);
#pragma unroll
        for (int i = 0; i < 4; i++) Bs[bn * TPAD + bk4 + i] = f2tf32(rb[i]);
        __syncthreads();

        if (kt + 1 < nk) {
            const int kb = (kt + 1) * TBK;
#pragma unroll
            for (int i = 0; i < 8; i++) {
                int m = am + i * 16;
                ra[i] = (kb + ak < K) ? __ldg(&A[(size_t)(m0 + m) * K + kb + ak]) : 0.f;
            }
#pragma unroll
            for (int i = 0; i < 4; i++) {
                int k = kb + bk4 + i;
                rb[i] = (k < K) ? __ldg(&W[(size_t)(n0 + bn) * K + k]) : 0.f;
            }
        }

#pragma unroll
        for (int ks = 0; ks < 2; ks++) {
            const int k = ks * 8;
            unsigned af[2][4];
#pragma unroll
            for (int mt = 0; mt < 2; mt++) {
                int row = wm * 32 + mt * 16;
                af[mt][0] = As[(row + g) * TPAD + k + t];
                af[mt][1] = As[(row + g + 8) * TPAD + k + t];
                af[mt][2] = As[(row + g) * TPAD + k + t + 4];
                af[mt][3] = As[(row + g + 8) * TPAD + k + t + 4];
            }
#pragma unroll
            for (int nt = 0; nt < 4; nt++) {
                int col = wn * 32 + nt * 8;
                unsigned b0 = Bs[(col + g) * TPAD + k + t];
                unsigned b1 = Bs[(col + g) * TPAD + k + t + 4];
#pragma unroll
                for (int mt = 0; mt < 2; mt++) mma_tf32(acc[mt][nt], af[mt], b0, b1);
            }
        }
        __syncthreads();
    }

#pragma unroll
    for (int mt = 0; mt < 2; mt++) {
#pragma unroll
        for (int nt = 0; nt < 4; nt++) {
            int row = m0 + wm * 32 + mt * 16 + g;
            int col = n0 + wn * 32 + nt * 8 + 2 * t;
            float b0 = bias[col], b1 = bias[col + 1];
            C[(size_t)row * N + col]           = acc[mt][nt][0] + b0;
            C[(size_t)row * N + col + 1]       = acc[mt][nt][1] + b1;
            C[(size_t)(row + 8) * N + col]     = acc[mt][nt][2] + b0;
            C[(size_t)(row + 8) * N + col + 1] = acc[mt][nt][3] + b1;
        }
    }
}

// ---------------- fp32 GEMM (tiny FC) --------------------------------------
#define GBM 128
#define GBN 64
#define GBK 8
__global__ __launch_bounds__(256) void gemm_bias_kernel(
    const float* __restrict__ A, const float* __restrict__ W,
    const float* __restrict__ bias, float* __restrict__ C,
    int M, int N, int K)
{
    __shared__ float As[GBK][GBM];
    __shared__ float Bs[GBK][GBN + 4];

    int tid = threadIdx.x;
    int tx = tid & 15;
    int ty = tid >> 4;
    int m0 = blockIdx.x * GBM;
    int n0 = blockIdx.y * GBN;

    float acc[8][4];
#pragma unroll
    for (int i = 0; i < 8; i++)
#pragma unroll
        for (int j = 0; j < 4; j++) acc[i][j] = 0.f;

    for (int k0 = 0; k0 < K; k0 += GBK) {
#pragma unroll
        for (int i = 0; i < 4; i++) {
            int idx = tid + i * 256;
            int m = idx >> 3, kk = idx & 7;
            float v = (k0 + kk < K) ? A[(size_t)(m0 + m) * K + k0 + kk] : 0.f;
            As[kk][m] = v;
        }
#pragma unroll
        for (int i = 0; i < 2; i++) {
            int idx = tid + i * 256;
            int n = idx >> 3, kk = idx & 7;
            float v = (k0 + kk < K) ? W[(size_t)(n0 + n) * K + k0 + kk] : 0.f;
            Bs[kk][n] = v;
        }
        __syncthreads();
#pragma unroll
        for (int kk = 0; kk < GBK; kk++) {
            float a[8], b[4];
#pragma unroll
            for (int i = 0; i < 8; i++) a[i] = As[kk][ty * 8 + i];
#pragma unroll
            for (int j = 0; j < 4; j++) b[j] = Bs[kk][tx * 4 + j];
#pragma unroll
            for (int i = 0; i < 8; i++)
#pragma unroll
                for (int j = 0; j < 4; j++) acc[i][j] = fmaf(a[i], b[j], acc[i][j]);
        }
        __syncthreads();
    }

    float bb[4];
#pragma unroll
    for (int j = 0; j < 4; j++) bb[j] = bias[n0 + tx * 4 + j];
#pragma unroll
    for (int i = 0; i < 8; i++) {
        size_t row = (size_t)(m0 + ty * 8 + i) * N + n0 + tx * 4;
#pragma unroll
        for (int j = 0; j < 4; j++) C[row + j] = acc[i][j] + bb[j];
    }
}

// ---------------- tensor-core persistent GRU recurrence --------------------
// 128 CTAs = 8 unit-groups (32 units -> 96 gate-rows) x 16 batch-groups (16 b).
// 192 threads = 6 warps; warp wid owns gate-rows [wid*16, wid*16+16), all 16 b.
// W_hh fragments live in registers (static across all 512 steps).
// Per step: h tile [16b x 256k] -> smem (tf32), 64 mma per warp, epilogue
// recombines r/z/n via smem and applies exact fp32 gate math.
#define RT_THREADS 192
#define RT_GRID 128
#define HP 260          // hs_tf row stride (words): banks 4g+t -> conflict-free
#define DSP 18          // Ds row stride
#define H32P 36         // hs32 row stride

__global__ __launch_bounds__(RT_THREADS, 1) void gru_rec_tc_kernel(
    const float* __restrict__ W_hh, const float* __restrict__ b_hh, int layer0)
{
    __shared__ unsigned hs_tf[16 * HP];   // h tile, tf32, [b][k]
    __shared__ float    hs32[16 * H32P];  // exact fp32 h_prev for own 32 units
    __shared__ float    Ds[96 * DSP];     // mma accums [gate-row][b]

    const int tid = threadIdx.x;
    const int wid = tid >> 5;             // 0..5
    const int lane = tid & 31;
    const int g = lane >> 2, t = lane & 3;

    const int ug = blockIdx.x >> 4;       // unit group 0..7
    const int bg = blockIdx.x & 15;       // batch group 0..15
    const int j0 = ug * 32;
    const int b0 = bg * 16;

    // ---- preload static A fragments (W_hh slice) into registers ----
    const int gate_w = wid >> 1;                       // this warp's gate
    const int wrow = gate_w * HH + j0 + (wid & 1) * 16; // W_hh row base
    unsigned a[32][4];
#pragma unroll
    for (int ks = 0; ks < 32; ks++) {
        int k = ks * 8;
        a[ks][0] = f2tf32(__ldg(&W_hh[(size_t)(wrow + g) * HH + k + t]));
        a[ks][1] = f2tf32(__ldg(&W_hh[(size_t)(wrow + g + 8) * HH + k + t]));
        a[ks][2] = f2tf32(__ldg(&W_hh[(size_t)(wrow + g) * HH + k + t + 4]));
        a[ks][3] = f2tf32(__ldg(&W_hh[(size_t)(wrow + g + 8) * HH + k + t + 4]));
    }

    // ---- epilogue thread assignment (tid < 128): unit ju, batches bq..bq+3 ----
    const int ju = tid >> 2;
    const int bq = (tid & 3) * 4;
    float bhr = 0.f, bhz = 0.f, bhn = 0.f;
    if (tid < 128) {
        bhr = __ldg(&b_hh[j0 + ju]);
        bhz = __ldg(&b_hh[HH + j0 + ju]);
        bhn = __ldg(&b_hh[2 * HH + j0 + ju]);
    }

    for (int s = 0; s < TT; s++) {
        // ---- phase 1: load h_{s-1} tile into smem (tf32 + exact fp32 slice) ----
        if (s == 0) {
            for (int idx = tid; idx < 16 * 64; idx += RT_THREADS) {
                int b = idx >> 6, k4 = (idx & 63) * 4;
                uint4 z = make_uint4(0u, 0u, 0u, 0u);
                *(uint4*)&hs_tf[b * HP + k4] = z;
            }
            for (int idx = tid; idx < 16 * 32; idx += RT_THREADS)
                hs32[(idx >> 5) * H32P + (idx & 31)] = 0.f;
        } else {
            for (int idx = tid; idx < 16 * 64; idx += RT_THREADS) {
                int b = idx >> 6, k4 = (idx & 63) * 4;
                size_t off = layer0
                    ? (((size_t)(b0 + b) * TT + (s - 1)) * HH + k4)
                    : ((size_t)(b0 + b) * HH + k4);
                const float* src = layer0 ? &g_out0[off] : &g_hbuf[s & 1][off];
                float4 v = __ldcg((const float4*)src);
                uint4 u;
                u.x = f2tf32(v.x); u.y = f2tf32(v.y);
                u.z = f2tf32(v.z); u.w = f2tf32(v.w);
                *(uint4*)&hs_tf[b * HP + k4] = u;
            }
            for (int idx = tid; idx < 16 * 32; idx += RT_THREADS) {
                int b = idx >> 5, u = idx & 31;
                size_t off = layer0
                    ? (((size_t)(b0 + b) * TT + (s - 1)) * HH + j0 + u)
                    : ((size_t)(b0 + b) * HH + j0 + u);
                hs32[b * H32P + u] = layer0 ? __ldcg(&g_out0[off]) : __ldcg(&g_hbuf[s & 1][off]);
            }
        }
        __syncthreads();

        // ---- phase 2: tensor-core matmul  D[96 x 16] = W_slice @ h^T ----
        float c0[4] = {0.f, 0.f, 0.f, 0.f};   // n-tile 0 (batch 0..7)
        float c1[4] = {0.f, 0.f, 0.f, 0.f};   // n-tile 1 (batch 8..15)
#pragma unroll
        for (int ks = 0; ks < 32; ks++) {
            int k = ks * 8;
            unsigned b00 = hs_tf[g * HP + k + t];
            unsigned b01 = hs_tf[g * HP + k + t + 4];
            unsigned b10 = hs_tf[(8 + g) * HP + k + t];
            unsigned b11 = hs_tf[(8 + g) * HP + k + t + 4];
            mma_tf32(c0, a[ks], b00, b01);
            mma_tf32(c1, a[ks], b10, b11);
        }
        // write accums to Ds
        {
            int lr = wid * 16 + g;
            *(float2*)&Ds[lr * DSP + 2 * t]            = make_float2(c0[0], c0[1]);
            *(float2*)&Ds[(lr + 8) * DSP + 2 * t]      = make_float2(c0[2], c0[3]);
            *(float2*)&Ds[lr * DSP + 8 + 2 * t]        = make_float2(c1[0], c1[1]);
            *(float2*)&Ds[(lr + 8) * DSP + 8 + 2 * t]  = make_float2(c1[2], c1[3]);
        }
        __syncthreads();

        // ---- phase 3: gates + state update (threads 0..127) ----
        if (tid < 128) {
#pragma unroll
            for (int i = 0; i < 4; i++) {
                int b = bq + i;
                int bglob = b0 + b;
                const float* xgp = &g_xg[((size_t)bglob * TT + s) * G3 + j0 + ju];
                float xr = __ldg(&xgp[0]);
                float xz = __ldg(&xgp[HH]);
                float xn = __ldg(&xgp[2 * HH]);
                float pr = Ds[ju * DSP + b];
                float pz = Ds[(32 + ju) * DSP + b];
                float pn = Ds[(64 + ju) * DSP + b];
                float hp = hs32[b * H32P + ju];
                float r = 1.f / (1.f + expf(-(xr + bhr + pr)));
                float z = 1.f / (1.f + expf(-(xz + bhz + pz)));
                float nn = tanhf(xn + r * (bhn + pn));
                float hnew = (1.f - z) * nn + z * hp;
                if (layer0)
                    g_out0[((size_t)bglob * TT + s) * HH + j0 + ju] = hnew;
                else
                    g_hbuf[(s + 1) & 1][(size_t)bglob * HH + j0 + ju] = hnew;
            }
        }

        // ---- phase 4: grid barrier ----
        __threadfence();
        __syncthreads();
        if (tid == 0) {
            atomicAdd(&g_cnt[s], 1u);
            while (*(volatile unsigned*)&g_cnt[s] < RT_GRID) { }
        }
        __syncthreads();
    }
}

// ---------------------------------------------------------------------------
extern "C" void kernel_launch(void* const* d_in, const int* in_sizes, int n_in,
                              void* d_out, int out_size)
{
    const float* x     = (const float*)d_in[0];
    const float* W_ih0 = (const float*)d_in[1];
    const float* W_hh0 = (const float*)d_in[2];
    const float* b_ih0 = (const float*)d_in[3];
    const float* b_hh0 = (const float*)d_in[4];
    const float* W_ih1 = (const float*)d_in[5];
    const float* W_hh1 = (const float*)d_in[6];
    const float* b_ih1 = (const float*)d_in[7];
    const float* b_hh1 = (const float*)d_in[8];
    const float* fc_W  = (const float*)d_in[9];
    const float* fc_b  = (const float*)d_in[10];
    float* out = (float*)d_out;

    float *xg, *out0, *hbuf;
    cudaGetSymbolAddress((void**)&xg,   g_xg);
    cudaGetSymbolAddress((void**)&out0, g_out0);
    cudaGetSymbolAddress((void**)&hbuf, g_hbuf);

    // layer 0 input preactivations: [BT,75] @ [768,75]^T   (TF32 tensor cores)
    tf32_gemm_bias_kernel<<<dim3(G3 / TBN, BT / TBM), 256>>>(x, W_ih0, b_ih0, xg, BT, G3, INDIM);
    // layer 0 recurrence -> g_out0 (tensor cores)
    zero_cnt_kernel<<<1, 512>>>();
    gru_rec_tc_kernel<<<RT_GRID, RT_THREADS>>>(W_hh0, b_hh0, 1);
    // layer 1 input preactivations: [BT,256] @ [768,256]^T (TF32 tensor cores)
    tf32_gemm_bias_kernel<<<dim3(G3 / TBN, BT / TBM), 256>>>(out0, W_ih1, b_ih1, xg, BT, G3, HH);
    // layer 1 recurrence -> g_hbuf[0] holds h_T (tensor cores)
    zero_cnt_kernel<<<1, 512>>>();
    gru_rec_tc_kernel<<<RT_GRID, RT_THREADS>>>(W_hh1, b_hh1, 0);
    // FC: [256,256] @ [256,256]^T + b (fp32, tiny)
    gemm_bias_kernel<<<dim3(BB / GBM, HH / GBN), 256>>>(hbuf, fc_W, fc_b, out, BB, HH, HH);
}

// round 4
// speedup vs baseline: 1.4858x; 1.4858x over previous
#include <cuda_runtime.h>
#include <math.h>

// Problem dims
#define BB 256
#define TT 512
#define HH 256
#define G3 768          // 3*H
#define INDIM 75
#define BT (BB*TT)      // 131072

// ---------------- scratch (device globals; no allocations allowed) ---------
__device__ float g_xg[(size_t)BB * TT * G3];     // input-gate preactivations (reused per layer)
__device__ float g_out0[(size_t)BB * TT * HH];   // layer-0 hidden states
__device__ float g_hT[BB * HH];                  // layer-1 final hidden state

__device__ __forceinline__ unsigned f2tf32(float v) {
    unsigned u;
    asm("cvt.rna.tf32.f32 %0, %1;" : "=r"(u) : "f"(v));
    return u;
}

__device__ __forceinline__ void mma_tf32(float c[4], const unsigned a[4], unsigned b0, unsigned b1) {
    asm volatile(
        "mma.sync.aligned.m16n8k8.row.col.f32.tf32.tf32.f32 "
        "{%0,%1,%2,%3}, {%4,%5,%6,%7}, {%8,%9}, {%0,%1,%2,%3};"
        : "+f"(c[0]), "+f"(c[1]), "+f"(c[2]), "+f"(c[3])
        : "r"(a[0]), "r"(a[1]), "r"(a[2]), "r"(a[3]), "r"(b0), "r"(b1));
}

__device__ __forceinline__ unsigned smem_u32(const void* p) {
    unsigned a;
    asm("{ .reg .u64 t; cvta.to.shared.u64 t, %1; cvt.u32.u64 %0, t; }" : "=r"(a) : "l"(p));
    return a;
}

__device__ __forceinline__ unsigned mapa_rank(unsigned addr, unsigned rank) {
    unsigned r;
    asm("mapa.shared::cluster.u32 %0, %1, %2;" : "=r"(r) : "r"(addr), "r"(rank));
    return r;
}

// ---------------- TF32 tensor-core GEMM: C = A[M,K] @ W[N,K]^T + bias ------
#define TBM 128
#define TBN 64
#define TBK 16
#define TPAD 20

__global__ __launch_bounds__(256) void tf32_gemm_bias_kernel(
    const float* __restrict__ A, const float* __restrict__ W,
    const float* __restrict__ bias, float* __restrict__ C,
    int M, int N, int K)
{
    __shared__ unsigned As[TBM * TPAD];
    __shared__ unsigned Bs[TBN * TPAD];

    const int tid = threadIdx.x;
    const int wid = tid >> 5, lane = tid & 31;
    const int g = lane >> 2, t = lane & 3;
    const int wm = wid & 3, wn = wid >> 2;
    const int m0 = blockIdx.y * TBM;
    const int n0 = blockIdx.x * TBN;

    float acc[2][4][4];
#pragma unroll
    for (int mt = 0; mt < 2; mt++)
#pragma unroll
        for (int nt = 0; nt < 4; nt++)
#pragma unroll
            for (int i = 0; i < 4; i++) acc[mt][nt][i] = 0.f;

    const int am = tid >> 4;
    const int ak = tid & 15;
    const int bn = tid >> 2;
    const int bk4 = (tid & 3) * 4;

    float ra[8], rb[4];
    const int nk = (K + TBK - 1) / TBK;

    {
#pragma unroll
        for (int i = 0; i < 8; i++) {
            int m = am + i * 16;
            ra[i] = (ak < K) ? __ldg(&A[(size_t)(m0 + m) * K + ak]) : 0.f;
        }
#pragma unroll
        for (int i = 0; i < 4; i++) {
            int k = bk4 + i;
            rb[i] = (k < K) ? __ldg(&W[(size_t)(n0 + bn) * K + k]) : 0.f;
        }
    }

    for (int kt = 0; kt < nk; kt++) {
#pragma unroll
        for (int i = 0; i < 8; i++) As[(am + i * 16) * TPAD + ak] = f2tf32(ra[i]);
#pragma unroll
        for (int i = 0; i < 4; i++) Bs[bn * TPAD + bk4 + i] = f2tf32(rb[i]);
        __syncthreads();

        if (kt + 1 < nk) {
            const int kb = (kt + 1) * TBK;
#pragma unroll
            for (int i = 0; i < 8; i++) {
                int m = am + i * 16;
                ra[i] = (kb + ak < K) ? __ldg(&A[(size_t)(m0 + m) * K + kb + ak]) : 0.f;
            }
#pragma unroll
            for (int i = 0; i < 4; i++) {
                int k = kb + bk4 + i;
                rb[i] = (k < K) ? __ldg(&W[(size_t)(n0 + bn) * K + k]) : 0.f;
            }
        }

#pragma unroll
        for (int ks = 0; ks < 2; ks++) {
            const int k = ks * 8;
            unsigned af[2][4];
#pragma unroll
            for (int mt = 0; mt < 2; mt++) {
                int row = wm * 32 + mt * 16;
                af[mt][0] = As[(row + g) * TPAD + k + t];
                af[mt][1] = As[(row + g + 8) * TPAD + k + t];
                af[mt][2] = As[(row + g) * TPAD + k + t + 4];
                af[mt][3] = As[(row + g + 8) * TPAD + k + t + 4];
            }
#pragma unroll
            for (int nt = 0; nt < 4; nt++) {
                int col = wn * 32 + nt * 8;
                unsigned b0 = Bs[(col + g) * TPAD + k + t];
                unsigned b1 = Bs[(col + g) * TPAD + k + t + 4];
#pragma unroll
                for (int mt = 0; mt < 2; mt++) mma_tf32(acc[mt][nt], af[mt], b0, b1);
            }
        }
        __syncthreads();
    }

#pragma unroll
    for (int mt = 0; mt < 2; mt++) {
#pragma unroll
        for (int nt = 0; nt < 4; nt++) {
            int row = m0 + wm * 32 + mt * 16 + g;
            int col = n0 + wn * 32 + nt * 8 + 2 * t;
            float b0 = bias[col], b1 = bias[col + 1];
            C[(size_t)row * N + col]           = acc[mt][nt][0] + b0;
            C[(size_t)row * N + col + 1]       = acc[mt][nt][1] + b1;
            C[(size_t)(row + 8) * N + col]     = acc[mt][nt][2] + b0;
            C[(size_t)(row + 8) * N + col + 1] = acc[mt][nt][3] + b1;
        }
    }
}

// ---------------- fp32 GEMM (tiny FC) --------------------------------------
#define GBM 128
#define GBN 64
#define GBK 8
__global__ __launch_bounds__(256) void gemm_bias_kernel(
    const float* __restrict__ A, const float* __restrict__ W,
    const float* __restrict__ bias, float* __restrict__ C,
    int M, int N, int K)
{
    __shared__ float As[GBK][GBM];
    __shared__ float Bs[GBK][GBN + 4];

    int tid = threadIdx.x;
    int tx = tid & 15;
    int ty = tid >> 4;
    int m0 = blockIdx.x * GBM;
    int n0 = blockIdx.y * GBN;

    float acc[8][4];
#pragma unroll
    for (int i = 0; i < 8; i++)
#pragma unroll
        for (int j = 0; j < 4; j++) acc[i][j] = 0.f;

    for (int k0 = 0; k0 < K; k0 += GBK) {
#pragma unroll
        for (int i = 0; i < 4; i++) {
            int idx = tid + i * 256;
            int m = idx >> 3, kk = idx & 7;
            float v = (k0 + kk < K) ? A[(size_t)(m0 + m) * K + k0 + kk] : 0.f;
            As[kk][m] = v;
        }
#pragma unroll
        for (int i = 0; i < 2; i++) {
            int idx = tid + i * 256;
            int n = idx >> 3, kk = idx & 7;
            float v = (k0 + kk < K) ? W[(size_t)(n0 + n) * K + k0 + kk] : 0.f;
            Bs[kk][n] = v;
        }
        __syncthreads();
#pragma unroll
        for (int kk = 0; kk < GBK; kk++) {
            float a[8], b[4];
#pragma unroll
            for (int i = 0; i < 8; i++) a[i] = As[kk][ty * 8 + i];
#pragma unroll
            for (int j = 0; j < 4; j++) b[j] = Bs[kk][tx * 4 + j];
#pragma unroll
            for (int i = 0; i < 8; i++)
#pragma unroll
                for (int j = 0; j < 4; j++) acc[i][j] = fmaf(a[i], b[j], acc[i][j]);
        }
        __syncthreads();
    }

    float bb[4];
#pragma unroll
    for (int j = 0; j < 4; j++) bb[j] = bias[n0 + tx * 4 + j];
#pragma unroll
    for (int i = 0; i < 8; i++) {
        size_t row = (size_t)(m0 + ty * 8 + i) * N + n0 + tx * 4;
#pragma unroll
        for (int j = 0; j < 4; j++) C[row + j] = acc[i][j] + bb[j];
    }
}

// ---------------- cluster-based persistent GRU recurrence ------------------
// 16 clusters x 8 CTAs. Cluster = 16 batches; CTA rank = 32 units (96 gate
// rows). W_hh fragments register-resident. Per step: mma on local smem h
// (double-buffered), epilogue pushes new h slice to all 8 cluster CTAs via
// st.shared::cluster, one cluster.sync per step. No global traffic on the
// critical path (xg prefetched under mma; g_out0 stores fire-and-forget).
#define CL 8
#define RT_THREADS 192
#define RT_GRID 128
#define HP 260          // hs_tf row stride (words): banks 4g+t -> conflict-free
#define DSP 17          // Ds row stride (reader conflict-free)
#define H32P 33         // hs32 row stride (reader conflict-free)

__global__ __launch_bounds__(RT_THREADS, 1) __cluster_dims__(CL, 1, 1)
void gru_rec_cluster_kernel(
    const float* __restrict__ W_hh, const float* __restrict__ b_hh, int layer0)
{
    __shared__ unsigned hs_tf[2][16 * HP];   // h (tf32) [b][unit], ping-pong
    __shared__ float    hs32[2][16 * H32P];  // own 32 units, exact fp32, ping-pong
    __shared__ float    Ds[96 * DSP];        // mma accums [gate-row][b]

    const int tid = threadIdx.x;
    const int wid = tid >> 5;             // 0..5
    const int lane = tid & 31;
    const int g = lane >> 2, t = lane & 3;

    unsigned rank;
    asm("mov.u32 %0, %%cluster_ctarank;" : "=r"(rank));
    const int bg = blockIdx.x >> 3;       // cluster id -> batch group 0..15
    const int j0 = (int)rank * 32;        // this CTA's unit base
    const int b0 = bg * 16;

    // ---- preload static A fragments (W_hh slice) into registers ----
    const int gate_w = wid >> 1;
    const int wrow = gate_w * HH + j0 + (wid & 1) * 16;
    unsigned a[32][4];
#pragma unroll
    for (int ks = 0; ks < 32; ks++) {
        int k = ks * 8;
        a[ks][0] = f2tf32(__ldg(&W_hh[(size_t)(wrow + g) * HH + k + t]));
        a[ks][1] = f2tf32(__ldg(&W_hh[(size_t)(wrow + g + 8) * HH + k + t]));
        a[ks][2] = f2tf32(__ldg(&W_hh[(size_t)(wrow + g) * HH + k + t + 4]));
        a[ks][3] = f2tf32(__ldg(&W_hh[(size_t)(wrow + g + 8) * HH + k + t + 4]));
    }

    // ---- epilogue assignment: thread (b, ju4) owns units ju4*4..+3, batch b ----
    const int eb = tid >> 3;              // 0..15 (tid<128)
    const int ju4 = tid & 7;              // 0..7
    float bhr[4], bhz[4], bhn[4];
    if (tid < 128) {
#pragma unroll
        for (int i = 0; i < 4; i++) {
            int j = j0 + ju4 * 4 + i;
            bhr[i] = __ldg(&b_hh[j]);
            bhz[i] = __ldg(&b_hh[HH + j]);
            bhn[i] = __ldg(&b_hh[2 * HH + j]);
        }
    }

    // precompute cluster-mapped destination addresses for the h push
    unsigned dst[CL];
    if (tid < 128) {
        unsigned l0 = smem_u32(&hs_tf[0][eb * HP + j0 + ju4 * 4]);
        unsigned l1 = smem_u32(&hs_tf[1][eb * HP + j0 + ju4 * 4]);
#pragma unroll
        for (int r = 0; r < CL; r++) dst[r] = mapa_rank(l0, (unsigned)r);
        // store buffer-1 delta once (same for all ranks)
        dst[0] = dst[0];  // keep
        // We derive buffer-1 addresses by adding (l1 - l0) to each mapped addr.
        unsigned d1 = l1 - l0;
        // stash delta in a register via reuse below
        bhr[0] = bhr[0]; // no-op
        // store delta in shared? simpler: recompute per use
        // (delta is uniform; keep in a variable)
        // We'll carry d1 separately:
        // (handled below via 'buf_delta')
        (void)d1;
    }
    unsigned buf_delta = 0;
    if (tid < 128) {
        unsigned l0 = smem_u32(&hs_tf[0][eb * HP + j0 + ju4 * 4]);
        unsigned l1 = smem_u32(&hs_tf[1][eb * HP + j0 + ju4 * 4]);
        buf_delta = l1 - l0;
    }

    // ---- init: zero both h buffers ----
    for (int idx = tid; idx < 16 * HP; idx += RT_THREADS) {
        hs_tf[0][idx] = 0u;
        hs_tf[1][idx] = 0u;
    }
    for (int idx = tid; idx < 16 * H32P; idx += RT_THREADS) {
        hs32[0][idx] = 0.f;
        hs32[1][idx] = 0.f;
    }
    asm volatile("barrier.cluster.arrive.aligned;" ::: "memory");
    asm volatile("barrier.cluster.wait.aligned;" ::: "memory");

    for (int s = 0; s < TT; s++) {
        const int cur = s & 1;
        const int nxt = cur ^ 1;

        // ---- xg prefetch (issued before mma; DRAM latency hides under mma) ----
        float4 xr4, xz4, xn4;
        if (tid < 128) {
            const float* xgp = &g_xg[((size_t)(b0 + eb) * TT + s) * G3 + j0 + ju4 * 4];
            xr4 = __ldcg((const float4*)&xgp[0]);
            xz4 = __ldcg((const float4*)&xgp[HH]);
            xn4 = __ldcg((const float4*)&xgp[2 * HH]);
        }

        // ---- tensor-core matmul: D[96 x 16] = W_slice @ h^T ----
        const unsigned* hb = hs_tf[cur];
        float c0[4] = {0.f, 0.f, 0.f, 0.f};
        float c1[4] = {0.f, 0.f, 0.f, 0.f};
#pragma unroll
        for (int ks = 0; ks < 32; ks++) {
            int k = ks * 8;
            unsigned b00 = hb[g * HP + k + t];
            unsigned b01 = hb[g * HP + k + t + 4];
            unsigned b10 = hb[(8 + g) * HP + k + t];
            unsigned b11 = hb[(8 + g) * HP + k + t + 4];
            mma_tf32(c0, a[ks], b00, b01);
            mma_tf32(c1, a[ks], b10, b11);
        }
        {
            int lr = wid * 16 + g;
            Ds[lr * DSP + 2 * t]           = c0[0];
            Ds[lr * DSP + 2 * t + 1]       = c0[1];
            Ds[(lr + 8) * DSP + 2 * t]     = c0[2];
            Ds[(lr + 8) * DSP + 2 * t + 1] = c0[3];
            Ds[lr * DSP + 8 + 2 * t]           = c1[0];
            Ds[lr * DSP + 8 + 2 * t + 1]       = c1[1];
            Ds[(lr + 8) * DSP + 8 + 2 * t]     = c1[2];
            Ds[(lr + 8) * DSP + 8 + 2 * t + 1] = c1[3];
        }
        __syncthreads();

        // ---- gates + state update + cluster-wide h push ----
        if (tid < 128) {
            float hnew[4];
#pragma unroll
            for (int i = 0; i < 4; i++) {
                int jl = ju4 * 4 + i;       // local unit 0..31
                float xr = (i == 0) ? xr4.x : (i == 1) ? xr4.y : (i == 2) ? xr4.z : xr4.w;
                float xz = (i == 0) ? xz4.x : (i == 1) ? xz4.y : (i == 2) ? xz4.z : xz4.w;
                float xn = (i == 0) ? xn4.x : (i == 1) ? xn4.y : (i == 2) ? xn4.z : xn4.w;
                float pr = Ds[jl * DSP + eb];
                float pz = Ds[(32 + jl) * DSP + eb];
                float pn = Ds[(64 + jl) * DSP + eb];
                float hp = hs32[cur][eb * H32P + jl];
                float r = 1.f / (1.f + expf(-(xr + bhr[i] + pr)));
                float z = 1.f / (1.f + expf(-(xz + bhz[i] + pz)));
                float nn = tanhf(xn + r * (bhn[i] + pn));
                hnew[i] = (1.f - z) * nn + z * hp;
            }
            // exact fp32 copy for own units (next step's h_prev)
#pragma unroll
            for (int i = 0; i < 4; i++)
                hs32[nxt][eb * H32P + ju4 * 4 + i] = hnew[i];
            // push tf32 h to all cluster CTAs' next buffer
            unsigned u0 = f2tf32(hnew[0]), u1 = f2tf32(hnew[1]);
            unsigned u2 = f2tf32(hnew[2]), u3 = f2tf32(hnew[3]);
            unsigned bofs = (nxt ? buf_delta : 0u);
#pragma unroll
            for (int r = 0; r < CL; r++) {
                asm volatile("st.shared::cluster.v4.b32 [%0], {%1,%2,%3,%4};"
                             :: "r"(dst[r] + bofs), "r"(u0), "r"(u1), "r"(u2), "r"(u3)
                             : "memory");
            }
            // global stores (off critical path)
            if (layer0) {
                float4 hv = make_float4(hnew[0], hnew[1], hnew[2], hnew[3]);
                *(float4*)&g_out0[((size_t)(b0 + eb) * TT + s) * HH + j0 + ju4 * 4] = hv;
            } else if (s == TT - 1) {
                float4 hv = make_float4(hnew[0], hnew[1], hnew[2], hnew[3]);
                *(float4*)&g_hT[(size_t)(b0 + eb) * HH + j0 + ju4 * 4] = hv;
            }
        }

        // ---- one cluster barrier per step (release/acquire covers DSMEM) ----
        asm volatile("barrier.cluster.arrive.aligned;" ::: "memory");
        asm volatile("barrier.cluster.wait.aligned;" ::: "memory");
    }
}

// ---------------------------------------------------------------------------
extern "C" void kernel_launch(void* const* d_in, const int* in_sizes, int n_in,
                              void* d_out, int out_size)
{
    const float* x     = (const float*)d_in[0];
    const float* W_ih0 = (const float*)d_in[1];
    const float* W_hh0 = (const float*)d_in[2];
    const float* b_ih0 = (const float*)d_in[3];
    const float* b_hh0 = (const float*)d_in[4];
    const float* W_ih1 = (const float*)d_in[5];
    const float* W_hh1 = (const float*)d_in[6];
    const float* b_ih1 = (const float*)d_in[7];
    const float* b_hh1 = (const float*)d_in[8];
    const float* fc_W  = (const float*)d_in[9];
    const float* fc_b  = (const float*)d_in[10];
    float* out = (float*)d_out;

    float *xg, *out0, *hT;
    cudaGetSymbolAddress((void**)&xg,   g_xg);
    cudaGetSymbolAddress((void**)&out0, g_out0);
    cudaGetSymbolAddress((void**)&hT,   g_hT);

    // layer 0 input preactivations: [BT,75] @ [768,75]^T   (TF32 tensor cores)
    tf32_gemm_bias_kernel<<<dim3(G3 / TBN, BT / TBM), 256>>>(x, W_ih0, b_ih0, xg, BT, G3, INDIM);
    // layer 0 recurrence -> g_out0 (cluster + DSMEM)
    gru_rec_cluster_kernel<<<RT_GRID, RT_THREADS>>>(W_hh0, b_hh0, 1);
    // layer 1 input preactivations: [BT,256] @ [768,256]^T (TF32 tensor cores)
    tf32_gemm_bias_kernel<<<dim3(G3 / TBN, BT / TBM), 256>>>(out0, W_ih1, b_ih1, xg, BT, G3, HH);
    // layer 1 recurrence -> g_hT
    gru_rec_cluster_kernel<<<RT_GRID, RT_THREADS>>>(W_hh1, b_hh1, 0);
    // FC: [256,256] @ [256,256]^T + b (fp32, tiny)
    gemm_bias_kernel<<<dim3(BB / GBM, HH / GBN), 256>>>(hT, fc_W, fc_b, out, BB, HH, HH);
}